// round 11
// baseline (speedup 1.0000x reference)
#include <cuda_runtime.h>

#define Pl  (128*128)
#define V   (128*128*128)
#define PX  136
#define PPl (130*136)
#define PV  (130*130*136)

typedef unsigned long long u64;

__device__ __forceinline__ u64 pk(float lo, float hi) {
    u64 r; asm("mov.b64 %0,{%1,%2};" : "=l"(r) : "f"(lo), "f"(hi)); return r;
}
__device__ __forceinline__ void fma2(u64 &d, u64 a, u64 b) {
    asm("fma.rn.f32x2 %0,%1,%2,%0;" : "+l"(d) : "l"(a), "l"(b));
}
__device__ __forceinline__ u64 mul2(u64 a, u64 b) {
    u64 r; asm("mul.rn.f32x2 %0,%1,%2;" : "=l"(r) : "l"(a), "l"(b)); return r;
}
__device__ __forceinline__ u64 add2(u64 a, u64 b) {
    u64 r; asm("add.rn.f32x2 %0,%1,%2;" : "=l"(r) : "l"(a), "l"(b)); return r;
}
__device__ __forceinline__ u64 abs2(u64 a) { return a & 0x7FFFFFFF7FFFFFFFULL; }
__device__ __forceinline__ float2 upk(u64 a) {
    float2 f; asm("mov.b64 {%0,%1},%2;" : "=f"(f.x), "=f"(f.y) : "l"(a)); return f;
}

// Padded scratch: [8][130][130][136], data voxel (z,y,x) at (z+1, y+1, x+4).
__device__ float g_xp[8 * PV];
__device__ float g_hp[8 * PV];
__device__ float g_tp[8 * PV];
__device__ float g_w [27 * V];   // unnormalized conv2 output (flat)

// ---------------------------------------------------------------------------
// pad_x: copy x into g_xp interior, zero g_xp halo
// ---------------------------------------------------------------------------
__global__ __launch_bounds__(160) void k_pad_x(const float* __restrict__ x)
{
    int row = blockIdx.x;                 // 8*130*130 rows
    int xx  = threadIdx.x;
    if (xx >= PX) return;
    int c   = row / (130 * 130);
    int rem = row % (130 * 130);
    int zz  = rem / 130;
    int yy  = rem % 130;
    bool halo = (zz == 0) | (zz == 129) | (yy == 0) | (yy == 129) | (xx < 4) | (xx >= 132);
    float v = 0.f;
    if (!halo)
        v = x[(size_t)c * V + (size_t)(zz - 1) * Pl + (yy - 1) * 128 + (xx - 4)];
    g_xp[(size_t)c * PV + zz * PPl + yy * PX + xx] = v;
}

// ---------------------------------------------------------------------------
// pad_halos: zero halos of g_hp and g_tp
// ---------------------------------------------------------------------------
__global__ __launch_bounds__(160) void k_pad_halos()
{
    int row = blockIdx.x;
    int xx  = threadIdx.x;
    if (xx >= PX) return;
    int c   = row / (130 * 130);
    int rem = row % (130 * 130);
    int zz  = rem / 130;
    int yy  = rem % 130;
    bool halo = (zz == 0) | (zz == 129) | (yy == 0) | (yy == 129) | (xx < 4) | (xx >= 132);
    if (halo) {
        size_t po = (size_t)c * PV + zz * PPl + yy * PX + xx;
        g_hp[po] = 0.f;
        g_tp[po] = 0.f;
    }
}

// ---------------------------------------------------------------------------
// conv1: g_xp -> g_hp = relu(conv3x3x3(x, w1) + b1), 8->8 channels.
// f32x2 lanes = (oc_even, oc_odd); inputs duplicated; 4 x per thread.
// ---------------------------------------------------------------------------
__global__ __launch_bounds__(256, 4) void k_conv1(const float* __restrict__ w1,
                                                  const float* __restrict__ b1)
{
    __shared__ float2 ws[8 * 27 * 4];   // [ic][tap][pair]
    __shared__ float2 bs[4];
    int tid = threadIdx.y * 32 + threadIdx.x;
    for (int i = tid; i < 864; i += 256) {
        int p = i & 3; int it = i >> 2; int t = it % 27; int ic = it / 27;
        ws[i] = make_float2(w1[(2 * p) * 216 + ic * 27 + t],
                            w1[(2 * p + 1) * 216 + ic * 27 + t]);
    }
    if (tid < 4) bs[tid] = make_float2(b1[2 * tid], b1[2 * tid + 1]);
    __syncthreads();

    int x0 = threadIdx.x * 4;
    int y  = blockIdx.x * 8 + threadIdx.y;
    int z  = blockIdx.y;

    u64 acc[4][4];   // [ocpair][x]
    #pragma unroll
    for (int p = 0; p < 4; p++) {
        u64 b = *reinterpret_cast<const u64*>(&bs[p]);
        acc[p][0] = b; acc[p][1] = b; acc[p][2] = b; acc[p][3] = b;
    }

    #pragma unroll 1
    for (int ic = 0; ic < 8; ic++) {
        const float* xc = g_xp + (size_t)ic * PV + (size_t)z * PPl + y * PX + x0 + 3;
        #pragma unroll
        for (int dz = 0; dz < 3; dz++) {
            #pragma unroll
            for (int dy = 0; dy < 3; dy++) {
                const float* r = xc + dz * PPl + dy * PX;
                float  i0 = r[0];
                float4 a4 = *reinterpret_cast<const float4*>(r + 1);
                float  i5 = r[5];
                u64 d[6];
                d[0] = pk(i0,   i0);   d[1] = pk(a4.x, a4.x);
                d[2] = pk(a4.y, a4.y); d[3] = pk(a4.z, a4.z);
                d[4] = pk(a4.w, a4.w); d[5] = pk(i5,   i5);
                const u64* wq = reinterpret_cast<const u64*>(&ws[(ic * 27 + (dz * 3 + dy) * 3) * 4]);
                #pragma unroll
                for (int s = 0; s < 3; s++) {
                    #pragma unroll
                    for (int p = 0; p < 4; p++) {
                        u64 w = wq[s * 4 + p];
                        fma2(acc[p][0], d[s + 0], w);
                        fma2(acc[p][1], d[s + 1], w);
                        fma2(acc[p][2], d[s + 2], w);
                        fma2(acc[p][3], d[s + 3], w);
                    }
                }
            }
        }
    }
    size_t ob = (size_t)(z + 1) * PPl + (y + 1) * PX + (x0 + 4);
    #pragma unroll
    for (int p = 0; p < 4; p++) {
        float2 v0 = upk(acc[p][0]), v1 = upk(acc[p][1]);
        float2 v2 = upk(acc[p][2]), v3 = upk(acc[p][3]);
        float4 lo = make_float4(fmaxf(v0.x, 0.f), fmaxf(v1.x, 0.f), fmaxf(v2.x, 0.f), fmaxf(v3.x, 0.f));
        float4 hi = make_float4(fmaxf(v0.y, 0.f), fmaxf(v1.y, 0.f), fmaxf(v2.y, 0.f), fmaxf(v3.y, 0.f));
        *reinterpret_cast<float4*>(&g_hp[(size_t)(2 * p)     * PV + ob]) = lo;
        *reinterpret_cast<float4*>(&g_hp[(size_t)(2 * p + 1) * PV + ob]) = hi;
    }
}

// ---------------------------------------------------------------------------
// conv2 v3: smem-staged inputs. g_hp -> g_w, 8->27 oc (grid.z = group of 9,
// 5 lane-pairs). Per ic: stage [3][10][136] input tile (16.3KB), inner loop
// reads via LDS (29cyc) instead of LDG (~240cyc). Weight taps padded to 48B
// so each s loads as 2x LDS.128 + 1x LDS.64.
// ---------------------------------------------------------------------------
__global__ __launch_bounds__(256, 3) void k_conv2(const float* __restrict__ w2)
{
    __shared__ float2 ws[8 * 27 * 6];      // [ic][tap][6] (slot 5 = pad)
    __shared__ float  s_in[3 * 10 * 136];  // [dz][yy][xx]

    int tid  = threadIdx.y * 32 + threadIdx.x;
    int base = blockIdx.z * 9;
    for (int i = tid; i < 8 * 27 * 5; i += 256) {
        int p = i % 5; int it = i / 5; int t = it % 27; int ic = it / 27;
        float wlo = w2[((base + 2 * p) * 8 + ic) * 27 + t];
        float whi = (2 * p + 1 < 9) ? w2[((base + 2 * p + 1) * 8 + ic) * 27 + t] : 0.f;
        ws[it * 6 + p] = make_float2(wlo, whi);
    }

    int x0 = threadIdx.x * 4;
    int y0 = blockIdx.x * 8;
    int ty = threadIdx.y;
    int z  = blockIdx.y;

    u64 acc[5][4];   // [ocpair][x]
    #pragma unroll
    for (int p = 0; p < 5; p++) { acc[p][0] = 0; acc[p][1] = 0; acc[p][2] = 0; acc[p][3] = 0; }

    float4* s4 = reinterpret_cast<float4*>(s_in);

    #pragma unroll 1
    for (int ic = 0; ic < 8; ic++) {
        __syncthreads();   // protect previous iteration's reads (no-op cost on iter 0 wrt ws)
        // stage tile: 3 z-planes x 10 rows x 34 float4
        const float* src = g_hp + (size_t)ic * PV + (size_t)z * PPl + y0 * PX;
        #pragma unroll
        for (int i = tid; i < 1020; i += 256) {
            int dzp = i / 340, rem = i % 340;
            int yy  = rem / 34, x4 = rem % 34;
            s4[(dzp * 10 + yy) * 34 + x4] =
                *reinterpret_cast<const float4*>(src + dzp * PPl + yy * PX + x4 * 4);
        }
        __syncthreads();

        #pragma unroll
        for (int dz = 0; dz < 3; dz++) {
            #pragma unroll
            for (int dy = 0; dy < 3; dy++) {
                const float* r = &s_in[(dz * 10 + ty + dy) * 136 + x0 + 3];
                float  i0 = r[0];
                float4 a4 = *reinterpret_cast<const float4*>(r + 1);
                float  i5 = r[5];
                u64 d[6];
                d[0] = pk(i0,   i0);   d[1] = pk(a4.x, a4.x);
                d[2] = pk(a4.y, a4.y); d[3] = pk(a4.z, a4.z);
                d[4] = pk(a4.w, a4.w); d[5] = pk(i5,   i5);
                int tap0 = ic * 27 + (dz * 3 + dy) * 3;
                #pragma unroll
                for (int s = 0; s < 3; s++) {
                    const float2* wb = &ws[(tap0 + s) * 6];
                    ulonglong2 w01 = *reinterpret_cast<const ulonglong2*>(wb);
                    ulonglong2 w23 = *reinterpret_cast<const ulonglong2*>(wb + 2);
                    u64        w4  = *reinterpret_cast<const u64*>(wb + 4);
                    fma2(acc[0][0], d[s + 0], w01.x);
                    fma2(acc[0][1], d[s + 1], w01.x);
                    fma2(acc[0][2], d[s + 2], w01.x);
                    fma2(acc[0][3], d[s + 3], w01.x);
                    fma2(acc[1][0], d[s + 0], w01.y);
                    fma2(acc[1][1], d[s + 1], w01.y);
                    fma2(acc[1][2], d[s + 2], w01.y);
                    fma2(acc[1][3], d[s + 3], w01.y);
                    fma2(acc[2][0], d[s + 0], w23.x);
                    fma2(acc[2][1], d[s + 1], w23.x);
                    fma2(acc[2][2], d[s + 2], w23.x);
                    fma2(acc[2][3], d[s + 3], w23.x);
                    fma2(acc[3][0], d[s + 0], w23.y);
                    fma2(acc[3][1], d[s + 1], w23.y);
                    fma2(acc[3][2], d[s + 2], w23.y);
                    fma2(acc[3][3], d[s + 3], w23.y);
                    fma2(acc[4][0], d[s + 0], w4);
                    fma2(acc[4][1], d[s + 1], w4);
                    fma2(acc[4][2], d[s + 2], w4);
                    fma2(acc[4][3], d[s + 3], w4);
                }
            }
        }
    }
    size_t ob = (size_t)z * Pl + (y0 + ty) * 128 + x0;
    #pragma unroll
    for (int o = 0; o < 9; o++) {
        int p = o >> 1, h = o & 1;
        float2 v0 = upk(acc[p][0]), v1 = upk(acc[p][1]);
        float2 v2 = upk(acc[p][2]), v3 = upk(acc[p][3]);
        float4 f = h ? make_float4(v0.y, v1.y, v2.y, v3.y)
                     : make_float4(v0.x, v1.x, v2.x, v3.x);
        *reinterpret_cast<float4*>(&g_w[(size_t)(base + o) * V + ob]) = f;
    }
}

// ---------------------------------------------------------------------------
// adaptive conv (proven R5 version): width 4, all 8 channels, fused L1 norm.
// ---------------------------------------------------------------------------
__global__ __launch_bounds__(256) void k_adapt(float* __restrict__ dout,
                                               int src, int dst)
{
    const float* in = (src == 0) ? g_xp : (src == 1 ? g_tp : g_hp);

    int x0 = threadIdx.x * 4;
    int y  = blockIdx.x * 8 + threadIdx.y;
    int z  = blockIdx.y;
    size_t ob  = (size_t)z * Pl + y * 128 + x0;
    size_t ibp = (size_t)z * PPl + y * PX + x0 + 3;

    u64 acc[8][2];
    #pragma unroll
    for (int c = 0; c < 8; c++) { acc[c][0] = 0; acc[c][1] = 0; }
    u64 nrm[2] = {0, 0};

    #pragma unroll
    for (int dz = 0; dz < 3; dz++) {
        #pragma unroll
        for (int dy = 0; dy < 3; dy++) {
            u64 q[3][2];
            #pragma unroll
            for (int s = 0; s < 3; s++) {
                const float* wr = g_w + (size_t)(dz * 9 + dy * 3 + s) * V + ob;
                float4 w0 = *reinterpret_cast<const float4*>(wr);
                q[s][0] = pk(w0.x, w0.y); q[s][1] = pk(w0.z, w0.w);
                nrm[0] = add2(nrm[0], abs2(q[s][0]));
                nrm[1] = add2(nrm[1], abs2(q[s][1]));
            }
            #pragma unroll
            for (int c = 0; c < 8; c++) {
                const float* r = in + (size_t)c * PV + ibp + dz * PPl + dy * PX;
                float  i0 = r[0];
                float4 a4 = *reinterpret_cast<const float4*>(r + 1);
                float  i5 = r[5];
                float iv[6] = {i0, a4.x, a4.y, a4.z, a4.w, i5};
                u64 p[5];
                #pragma unroll
                for (int k = 0; k < 5; k++) p[k] = pk(iv[k], iv[k + 1]);
                #pragma unroll
                for (int s = 0; s < 3; s++) {
                    fma2(acc[c][0], p[s + 0], q[s][0]);
                    fma2(acc[c][1], p[s + 2], q[s][1]);
                }
            }
        }
    }

    u64 rn[2];
    #pragma unroll
    for (int j = 0; j < 2; j++) {
        float2 n2 = upk(nrm[j]);
        rn[j] = pk(1.f / fmaxf(n2.x, 1e-12f), 1.f / fmaxf(n2.y, 1e-12f));
    }

    if (dst == 0) {
        #pragma unroll
        for (int c = 0; c < 8; c++) {
            float2 v0 = upk(mul2(acc[c][0], rn[0]));
            float2 v1 = upk(mul2(acc[c][1], rn[1]));
            *reinterpret_cast<float4*>(&dout[(size_t)c * V + ob]) =
                make_float4(v0.x, v0.y, v1.x, v1.y);
        }
    } else {
        float* out = (dst == 1) ? g_tp : g_hp;
        size_t op = (size_t)(z + 1) * PPl + (y + 1) * PX + (x0 + 4);
        #pragma unroll
        for (int c = 0; c < 8; c++) {
            float2 v0 = upk(mul2(acc[c][0], rn[0]));
            float2 v1 = upk(mul2(acc[c][1], rn[1]));
            *reinterpret_cast<float4*>(&out[(size_t)c * PV + op]) =
                make_float4(v0.x, v0.y, v1.x, v1.y);
        }
    }
}

// ---------------------------------------------------------------------------
extern "C" void kernel_launch(void* const* d_in, const int* in_sizes, int n_in,
                              void* d_out, int out_size)
{
    const float* x  = (const float*)d_in[0];
    const float* w1 = (n_in > 1) ? (const float*)d_in[1] : nullptr;
    const float* b1 = (n_in > 2) ? (const float*)d_in[2] : nullptr;
    const float* w2 = (n_in > 3) ? (const float*)d_in[3] : nullptr;
    for (int i = 0; i < n_in; i++) {
        switch (in_sizes[i]) {
            case 8 * V: x  = (const float*)d_in[i]; break;
            case 1728:  w1 = (const float*)d_in[i]; break;
            case 8:     b1 = (const float*)d_in[i]; break;
            case 5832:  w2 = (const float*)d_in[i]; break;
            default: break;
        }
    }

    int nrow = 8 * 130 * 130;
    dim3 cblk(32, 8);
    dim3 cg(16, 128);

    // Profiled launch is #4 -> k_conv2 sits there.
    k_pad_x<<<nrow, 160>>>(x);                   // 1
    k_conv1<<<cg, cblk>>>(w1, b1);               // 2
    k_pad_halos<<<nrow, 160>>>();                // 3
    k_conv2<<<dim3(16, 128, 3), cblk>>>(w2);     // 4  <-- profiled
    float* out = (float*)d_out;
    dim3 ablk(32, 8);
    k_adapt<<<cg, ablk>>>(out, 0, 1);            // 5: g_xp -> g_tp
    k_adapt<<<cg, ablk>>>(out, 1, 2);            // 6: g_tp -> g_hp
    k_adapt<<<cg, ablk>>>(out, 2, 0);            // 7: g_hp -> d_out
}